// round 10
// baseline (speedup 1.0000x reference)
#include <cuda_runtime.h>
#include <math.h>

typedef unsigned long long ull;

#define IMG 512
#define BW  288     // threads per block = columns per strip

__device__ double g_acc;

__global__ void init_acc_kernel() { g_acc = 0.0; }

__global__ void finalize_kernel(float* out, double scale) {
    out[0] = (float)(g_acc * scale);
}

// ---- f32x2 packed helpers ----
__device__ __forceinline__ ull pack2(float lo, float hi) {
    ull r;
    asm("mov.b64 %0, {%1, %2};" : "=l"(r) : "f"(lo), "f"(hi));
    return r;
}
__device__ __forceinline__ void unpack2(ull v, float& lo, float& hi) {
    asm("mov.b64 {%0, %1}, %2;" : "=f"(lo), "=f"(hi) : "l"(v));
}
__device__ __forceinline__ void ffma2(ull& d, ull a, ull b) {
    asm("fma.rn.f32x2 %0, %1, %2, %0;" : "+l"(d) : "l"(a), "l"(b));
}
__device__ __forceinline__ ull fma2v(ull a, ull b, ull c) {   // a*b + c
    ull d;
    asm("fma.rn.f32x2 %0, %1, %2, %3;" : "=l"(d) : "l"(a), "l"(b), "l"(c));
    return d;
}
__device__ __forceinline__ ull mul2(ull a, ull b) {
    ull d;
    asm("mul.rn.f32x2 %0, %1, %2;" : "=l"(d) : "l"(a), "l"(b));
    return d;
}

// Batched streaming register-systolic kernel. One thread = one column.
// U rows per __syncthreads using double-buffered (phase) row rings.
// Pipeline lags (in row-iteration units p):
//   mean/S2 complete row p-R;  xc[p-R] written to next phase's buffer;
//   hc3/hc4 convolve xc row p-U-R (published last batch);
//   m3/m4 complete output row p-U-2R  ->  o_idx = p - U - 4R.
template <int K, int MINB, int CH>
__global__ __launch_bounds__(BW, MINB)
void stat_stream_kernel(const float* __restrict__ pred,
                        const float* __restrict__ tgt)
{
    constexpr int R    = K / 2;
    constexpr int U    = R + 2;           // rows per batch
    constexpr int D    = 2 * U;           // var-ring depth (2 phases)
    constexpr int UWB  = BW - 4 * R;      // useful output columns per block
    constexpr int NRAW = CH + 4 * R + U;  // row-iterations needed
    constexpr int NB2  = (NRAW + D - 1) / D;   // batch PAIRS

    // smem: pad(8) | xc0 | x0 | xc1 | x1 | pad(8)   each U*BW u64
    __shared__ __align__(16) ull sbuf[4 * U * BW + 16];
    __shared__ float wsum[BW / 32];
    ull* const xc0 = sbuf + 8;
    ull* const xb0 = xc0 + U * BW;
    ull* const xc1 = xb0 + U * BW;
    ull* const xb1 = xc1 + U * BW;

    const int tid = threadIdx.x;
    const int c0  = blockIdx.y * CH;
    const int col = blockIdx.x * UWB - 2 * R + tid;
    const bool incol = (unsigned)col < (unsigned)IMG;
    const bool uc = (tid >= 2 * R) && (tid < 2 * R + UWB) && incol;
    const size_t plane = (size_t)blockIdx.z * (size_t)(IMG * IMG);

    // normalized 1D gaussian, packed into both lanes
    ull gp[K];
    {
        const float sigma = (float)K / 6.0f;
        const float inv2s2 = 1.0f / (2.0f * sigma * sigma);
        float gt[K];
        float s = 0.0f;
#pragma unroll
        for (int j = 0; j < K; ++j) {
            float c = (float)(j - K / 2);
            gt[j] = expf(-c * c * inv2s2);
            s += gt[j];
        }
        float inv = 1.0f / s;
#pragma unroll
        for (int j = 0; j < K; ++j) { float w = gt[j] * inv; gp[j] = pack2(w, w); }
    }
    const ull NEG1 = pack2(-1.0f, -1.0f);

    // systolic partials + packed variance ring
    ull Am[K - 1], As[K - 1], A3[K - 1], A4[K - 1];
#pragma unroll
    for (int i = 0; i < K - 1; ++i) { Am[i] = 0; As[i] = 0; A3[i] = 0; A4[i] = 0; }
    ull vr[D];
#pragma unroll
    for (int i = 0; i < D; ++i) vr[i] = 0;

    const int r0 = c0 - 2 * R;
    const float* pp = pred + plane + (long long)r0 * IMG + col;
    const float* pt = tgt  + plane + (long long)r0 * IMG + col;

    // preamble: fill x phase-0 rows r0..r0+U-1; zero everything else
#pragma unroll
    for (int u = 0; u < U; ++u) {
        int rr = r0 + u;
        float a = 0.0f, b = 0.0f;
        if (incol && ((unsigned)rr < (unsigned)IMG)) { a = pp[0]; b = pt[0]; }
        xb0[u * BW + tid] = pack2(a, b);
        xc0[u * BW + tid] = 0ull;
        xb1[u * BW + tid] = 0ull;
        xc1[u * BW + tid] = 0ull;
        pp += IMG; pt += IMG;
    }
    if (tid < 8) { sbuf[tid] = 0ull; sbuf[4 * U * BW + 8 + tid] = 0ull; }

    float acc = 0.0f;

#pragma unroll 1
    for (int bp = 0; bp < NB2; ++bp) {
#pragma unroll
        for (int ph = 0; ph < 2; ++ph) {
            const int p0 = (bp * 2 + ph) * U;
            ull* const xbC = ph ? xb1 : xb0;   // current-phase buffers (read)
            ull* const xcC = ph ? xc1 : xc0;
            ull* const xbN = ph ? xb0 : xb1;   // next-phase buffers (write)
            ull* const xcN = ph ? xc0 : xc1;

            __syncthreads();   // publishes of previous batch complete

#pragma unroll
            for (int u = 0; u < U; ++u) {
                const int p = p0 + u;

                // prefetch x row p+U straight into next phase's buffer
                {
                    int rr = r0 + p + U;
                    float a = 0.0f, b = 0.0f;
                    if (incol && ((unsigned)rr < (unsigned)IMG)) { a = pp[0]; b = pt[0]; }
                    xbN[u * BW + tid] = pack2(a, b);
                    pp += IMG; pt += IMG;
                }

                // ---- level-1 horizontal convs on x row p ----
                ull h1 = 0ull, hs2 = 0ull;
                {
                    const ull* xb = xbC + u * BW + (tid - R);
#pragma unroll
                    for (int j = 0; j < K; ++j) {
                        ull t = xb[j];
                        ffma2(h1, gp[j], t);
                        ull t2 = mul2(t, t);
                        ffma2(hs2, gp[j], t2);
                    }
                }

                // ---- mean/S2 vertical systolic: completes row p-R ----
                ull meanc = Am[0]; ffma2(meanc, gp[K - 1], h1);
                ull S2c   = As[0]; ffma2(S2c,   gp[K - 1], hs2);
#pragma unroll
                for (int i = 0; i < K - 2; ++i) {
                    ull a = Am[i + 1]; ffma2(a, gp[K - 2 - i], h1);  Am[i] = a;
                    ull b = As[i + 1]; ffma2(b, gp[K - 2 - i], hs2); As[i] = b;
                }
                Am[K - 2] = mul2(gp[0], h1);
                As[K - 2] = mul2(gp[0], hs2);

                // ---- xc at row p-R -> next phase's xc buffer ----
                {
                    // x row p-R: own column only; u<R -> previous batch (other phase)
                    ull xm = (u < R) ? xbN[(U - R + u) * BW + tid]
                                     : xbC[(u - R) * BW + tid];
                    int m_row = r0 + p - R;
                    bool mimg = incol && ((unsigned)m_row < (unsigned)IMG);
                    ull xcv = fma2v(meanc, NEG1, xm);
                    xcN[u * BW + tid] = mimg ? xcv : 0ull;
                }

                // ---- features at row p-R: |dmean|+|dvar|, store packed var ----
                {
                    const int m_idx = p - 3 * R;
                    if ((unsigned)m_idx < (unsigned)CH) {
                        float mp, mt, sp, st;
                        unpack2(meanc, mp, mt);
                        unpack2(S2c,   sp, st);
                        float vp = fmaxf(fmaf(-mp, mp, sp), 1e-8f);
                        float vt = fmaxf(fmaf(-mt, mt, st), 1e-8f);
                        if (uc) acc += fabsf(mp - mt) + fabsf(vp - vt);
                        vr[ph * U + u] = pack2(vp, vt);
                    }
                }

                // ---- level-2 horizontal convs on xc row p-U-R ----
                ull hc3 = 0ull, hc4 = 0ull;
                {
                    const ull* cb = xcC + u * BW + (tid - R);
#pragma unroll
                    for (int j = 0; j < K; ++j) {
                        ull s  = cb[j];
                        ull s2 = mul2(s, s);
                        ull c3 = mul2(s2, s);
                        ull c4 = mul2(s2, s2);
                        ffma2(hc3, gp[j], c3);
                        ffma2(hc4, gp[j], c4);
                    }
                }

                // ---- m3/m4 vertical systolic: completes output row p-U-2R ----
                ull m3c = A3[0]; ffma2(m3c, gp[K - 1], hc3);
                ull m4c = A4[0]; ffma2(m4c, gp[K - 1], hc4);
#pragma unroll
                for (int i = 0; i < K - 2; ++i) {
                    ull a = A3[i + 1]; ffma2(a, gp[K - 2 - i], hc3); A3[i] = a;
                    ull b = A4[i + 1]; ffma2(b, gp[K - 2 - i], hc4); A4[i] = b;
                }
                A3[K - 2] = mul2(gp[0], hc3);
                A4[K - 2] = mul2(gp[0], hc4);

                {
                    const int o_idx = p - U - 4 * R;
                    if (((unsigned)o_idx < (unsigned)CH) && uc) {
                        const int slot = (ph * U + u + U - R) % D;  // var of this row
                        float vp, vt;
                        unpack2(vr[slot], vp, vt);
                        float m3p, m3t, m4p, m4t;
                        unpack2(m3c, m3p, m3t);
                        unpack2(m4c, m4p, m4t);
                        float sdp = sqrtf(vp), sdt = sqrtf(vt);
                        float skp = __fdividef(m3p, fmaf(sdp, vp, 1e-8f));
                        float skt = __fdividef(m3t, fmaf(sdt, vt, 1e-8f));
                        float kup = __fdividef(m4p, fmaf(vp, vp, 1e-8f));
                        float kut = __fdividef(m4t, fmaf(vt, vt, 1e-8f));
                        acc += 0.5f   * fabsf(skp - skt)
                             + 0.001f * fabsf(kup - kut);
                    }
                }
            }
        }
    }

    // ---- block reduction, atomic accumulate ----
#pragma unroll
    for (int off = 16; off > 0; off >>= 1)
        acc += __shfl_xor_sync(0xffffffffu, acc, off);
    if ((tid & 31) == 0) wsum[tid >> 5] = acc;
    __syncthreads();
    if (tid < 32) {
        float v = (tid < BW / 32) ? wsum[tid] : 0.0f;
#pragma unroll
        for (int off = 16; off > 0; off >>= 1)
            v += __shfl_xor_sync(0xffffffffu, v, off);
        if (tid == 0) atomicAdd(&g_acc, (double)v);
    }
}

extern "C" void kernel_launch(void* const* d_in, const int* in_sizes, int n_in,
                              void* d_out, int out_size) {
    const float* pred = (const float*)d_in[0];
    const float* tgt  = (const float*)d_in[1];
    float* out = (float*)d_out;

    const int npix = in_sizes[0];               // 16*3*512*512
    const int planes = npix / (IMG * IMG);      // 48

    constexpr int CH = 128;
    dim3 grid(2, IMG / CH, planes);             // 2 strips x 4 chunks x planes

    init_acc_kernel<<<1, 1>>>();
    stat_stream_kernel<3, 3, CH><<<grid, BW>>>(pred, tgt);
    stat_stream_kernel<5, 2, CH><<<grid, BW>>>(pred, tgt);
    stat_stream_kernel<7, 2, CH><<<grid, BW>>>(pred, tgt);

    const double scale = 1.0 / (12.0 * (double)npix);
    finalize_kernel<<<1, 1>>>(out, scale);
}

// round 11
// speedup vs baseline: 1.0296x; 1.0296x over previous
#include <cuda_runtime.h>
#include <math.h>

typedef unsigned long long ull;

#define IMG 512
#define BW  288     // threads per block = columns per strip
#define CHR 64      // output rows per chunk

__device__ double g_acc;

__global__ void init_acc_kernel() { g_acc = 0.0; }

__global__ void finalize_kernel(float* out, double scale) {
    out[0] = (float)(g_acc * scale);
}

// ---- f32x2 packed helpers ----
__device__ __forceinline__ ull pack2(float lo, float hi) {
    ull r;
    asm("mov.b64 %0, {%1, %2};" : "=l"(r) : "f"(lo), "f"(hi));
    return r;
}
__device__ __forceinline__ void unpack2(ull v, float& lo, float& hi) {
    asm("mov.b64 {%0, %1}, %2;" : "=f"(lo), "=f"(hi) : "l"(v));
}
__device__ __forceinline__ void ffma2(ull& d, ull a, ull b) {
    asm("fma.rn.f32x2 %0, %1, %2, %0;" : "+l"(d) : "l"(a), "l"(b));
}
__device__ __forceinline__ ull fma2v(ull a, ull b, ull c) {   // a*b + c
    ull d;
    asm("fma.rn.f32x2 %0, %1, %2, %3;" : "=l"(d) : "l"(a), "l"(b), "l"(c));
    return d;
}
__device__ __forceinline__ ull mul2(ull a, ull b) {
    ull d;
    asm("mul.rn.f32x2 %0, %1, %2;" : "=l"(d) : "l"(a), "l"(b));
    return d;
}

// Batched streaming register-systolic pipeline. One thread = one column.
// U rows per __syncthreads using double-buffered (phase) row rings.
// Pipeline lags (in row-iteration units p):
//   mean/S2 complete row p-R;  xc[p-R] written to next phase's buffer;
//   hc3/hc4 convolve xc row p-U-R (published last batch);
//   m3/m4 complete output row p-U-2R  ->  o_idx = p - U - 4R.
template <int K, int CH>
__device__ __forceinline__ void run_stream(const float* __restrict__ pred,
                                           const float* __restrict__ tgt,
                                           ull* sbuf, float* wsum,
                                           int bx, int by, int plane_id)
{
    constexpr int R    = K / 2;
    constexpr int U    = R + 2;           // rows per batch
    constexpr int D    = 2 * U;           // var-ring depth (2 phases)
    constexpr int UWB  = BW - 4 * R;      // useful output columns per block
    constexpr int NRAW = CH + 4 * R + U;  // row-iterations needed
    constexpr int NB2  = (NRAW + D - 1) / D;   // batch PAIRS

    ull* const xc0 = sbuf + 8;
    ull* const xb0 = xc0 + U * BW;
    ull* const xc1 = xb0 + U * BW;
    ull* const xb1 = xc1 + U * BW;

    const int tid = threadIdx.x;
    const int c0  = by * CH;
    const int col = bx * UWB - 2 * R + tid;
    const bool incol = (unsigned)col < (unsigned)IMG;
    const bool uc = (tid >= 2 * R) && (tid < 2 * R + UWB) && incol;
    const size_t plane = (size_t)plane_id * (size_t)(IMG * IMG);

    // normalized 1D gaussian, packed into both lanes
    ull gp[K];
    {
        const float sigma = (float)K / 6.0f;
        const float inv2s2 = 1.0f / (2.0f * sigma * sigma);
        float gt[K];
        float s = 0.0f;
#pragma unroll
        for (int j = 0; j < K; ++j) {
            float c = (float)(j - K / 2);
            gt[j] = expf(-c * c * inv2s2);
            s += gt[j];
        }
        float inv = 1.0f / s;
#pragma unroll
        for (int j = 0; j < K; ++j) { float w = gt[j] * inv; gp[j] = pack2(w, w); }
    }
    const ull NEG1 = pack2(-1.0f, -1.0f);

    // systolic partials + packed variance ring
    ull Am[K - 1], As[K - 1], A3[K - 1], A4[K - 1];
#pragma unroll
    for (int i = 0; i < K - 1; ++i) { Am[i] = 0; As[i] = 0; A3[i] = 0; A4[i] = 0; }
    ull vr[D];
#pragma unroll
    for (int i = 0; i < D; ++i) vr[i] = 0;

    const int r0 = c0 - 2 * R;
    const float* pp = pred + plane + (long long)r0 * IMG + col;
    const float* pt = tgt  + plane + (long long)r0 * IMG + col;

    // preamble: fill x phase-0 rows r0..r0+U-1; zero everything else
#pragma unroll
    for (int u = 0; u < U; ++u) {
        int rr = r0 + u;
        float a = 0.0f, b = 0.0f;
        if (incol && ((unsigned)rr < (unsigned)IMG)) { a = pp[0]; b = pt[0]; }
        xb0[u * BW + tid] = pack2(a, b);
        xc0[u * BW + tid] = 0ull;
        xb1[u * BW + tid] = 0ull;
        xc1[u * BW + tid] = 0ull;
        pp += IMG; pt += IMG;
    }
    if (tid < 8) { sbuf[tid] = 0ull; sbuf[4 * U * BW + 8 + tid] = 0ull; }

    float acc = 0.0f;

#pragma unroll 1
    for (int bp = 0; bp < NB2; ++bp) {
#pragma unroll
        for (int ph = 0; ph < 2; ++ph) {
            const int p0 = (bp * 2 + ph) * U;
            ull* const xbC = ph ? xb1 : xb0;   // current-phase buffers (read)
            ull* const xcC = ph ? xc1 : xc0;
            ull* const xbN = ph ? xb0 : xb1;   // next-phase buffers (write)
            ull* const xcN = ph ? xc0 : xc1;

            __syncthreads();   // publishes of previous batch complete

#pragma unroll
            for (int u = 0; u < U; ++u) {
                const int p = p0 + u;

                // prefetch x row p+U straight into next phase's buffer
                {
                    int rr = r0 + p + U;
                    float a = 0.0f, b = 0.0f;
                    if (incol && ((unsigned)rr < (unsigned)IMG)) { a = pp[0]; b = pt[0]; }
                    xbN[u * BW + tid] = pack2(a, b);
                    pp += IMG; pt += IMG;
                }

                // ---- level-1 horizontal convs on x row p ----
                ull h1 = 0ull, hs2 = 0ull;
                {
                    const ull* xb = xbC + u * BW + (tid - R);
#pragma unroll
                    for (int j = 0; j < K; ++j) {
                        ull t = xb[j];
                        ffma2(h1, gp[j], t);
                        ull t2 = mul2(t, t);
                        ffma2(hs2, gp[j], t2);
                    }
                }

                // ---- mean/S2 vertical systolic: completes row p-R ----
                ull meanc = Am[0]; ffma2(meanc, gp[K - 1], h1);
                ull S2c   = As[0]; ffma2(S2c,   gp[K - 1], hs2);
#pragma unroll
                for (int i = 0; i < K - 2; ++i) {
                    ull a = Am[i + 1]; ffma2(a, gp[K - 2 - i], h1);  Am[i] = a;
                    ull b = As[i + 1]; ffma2(b, gp[K - 2 - i], hs2); As[i] = b;
                }
                Am[K - 2] = mul2(gp[0], h1);
                As[K - 2] = mul2(gp[0], hs2);

                // ---- xc at row p-R -> next phase's xc buffer ----
                {
                    // x row p-R: own column only; u<R -> previous batch (other phase)
                    ull xm = (u < R) ? xbN[(U - R + u) * BW + tid]
                                     : xbC[(u - R) * BW + tid];
                    int m_row = r0 + p - R;
                    bool mimg = incol && ((unsigned)m_row < (unsigned)IMG);
                    ull xcv = fma2v(meanc, NEG1, xm);
                    xcN[u * BW + tid] = mimg ? xcv : 0ull;
                }

                // ---- features at row p-R: |dmean|+|dvar|, store packed var ----
                {
                    const int m_idx = p - 3 * R;
                    if ((unsigned)m_idx < (unsigned)CH) {
                        float mp, mt, sp, st;
                        unpack2(meanc, mp, mt);
                        unpack2(S2c,   sp, st);
                        float vp = fmaxf(fmaf(-mp, mp, sp), 1e-8f);
                        float vt = fmaxf(fmaf(-mt, mt, st), 1e-8f);
                        if (uc) acc += fabsf(mp - mt) + fabsf(vp - vt);
                        vr[ph * U + u] = pack2(vp, vt);
                    }
                }

                // ---- level-2 horizontal convs on xc row p-U-R ----
                ull hc3 = 0ull, hc4 = 0ull;
                {
                    const ull* cb = xcC + u * BW + (tid - R);
#pragma unroll
                    for (int j = 0; j < K; ++j) {
                        ull s  = cb[j];
                        ull s2 = mul2(s, s);
                        ull c3 = mul2(s2, s);
                        ull c4 = mul2(s2, s2);
                        ffma2(hc3, gp[j], c3);
                        ffma2(hc4, gp[j], c4);
                    }
                }

                // ---- m3/m4 vertical systolic: completes output row p-U-2R ----
                ull m3c = A3[0]; ffma2(m3c, gp[K - 1], hc3);
                ull m4c = A4[0]; ffma2(m4c, gp[K - 1], hc4);
#pragma unroll
                for (int i = 0; i < K - 2; ++i) {
                    ull a = A3[i + 1]; ffma2(a, gp[K - 2 - i], hc3); A3[i] = a;
                    ull b = A4[i + 1]; ffma2(b, gp[K - 2 - i], hc4); A4[i] = b;
                }
                A3[K - 2] = mul2(gp[0], hc3);
                A4[K - 2] = mul2(gp[0], hc4);

                {
                    const int o_idx = p - U - 4 * R;
                    if (((unsigned)o_idx < (unsigned)CH) && uc) {
                        const int slot = (ph * U + u + U - R) % D;  // var of this row
                        float vp, vt;
                        unpack2(vr[slot], vp, vt);
                        float m3p, m3t, m4p, m4t;
                        unpack2(m3c, m3p, m3t);
                        unpack2(m4c, m4p, m4t);
                        float sdp = sqrtf(vp), sdt = sqrtf(vt);
                        float skp = __fdividef(m3p, fmaf(sdp, vp, 1e-8f));
                        float skt = __fdividef(m3t, fmaf(sdt, vt, 1e-8f));
                        float kup = __fdividef(m4p, fmaf(vp, vp, 1e-8f));
                        float kut = __fdividef(m4t, fmaf(vt, vt, 1e-8f));
                        acc += 0.5f   * fabsf(skp - skt)
                             + 0.001f * fabsf(kup - kut);
                    }
                }
            }
        }
    }

    // ---- block reduction, atomic accumulate ----
#pragma unroll
    for (int off = 16; off > 0; off >>= 1)
        acc += __shfl_xor_sync(0xffffffffu, acc, off);
    if ((tid & 31) == 0) wsum[tid >> 5] = acc;
    __syncthreads();
    if (tid < 32) {
        float v = (tid < BW / 32) ? wsum[tid] : 0.0f;
#pragma unroll
        for (int off = 16; off > 0; off >>= 1)
            v += __shfl_xor_sync(0xffffffffu, v, off);
        if (tid == 0) atomicAdd(&g_acc, (double)v);
    }
}

// One merged kernel: blockIdx.z encodes (plane, window). Window selection is
// uniform per block so the internal __syncthreads are safe.
__global__ __launch_bounds__(BW, 2)
void stat_all_kernel(const float* __restrict__ pred,
                     const float* __restrict__ tgt)
{
    // sized for K=7 (U=5): pad | xc0 | x0 | xc1 | x1 | pad
    __shared__ __align__(16) ull sbuf[4 * 5 * BW + 16];
    __shared__ float wsum[BW / 32];

    const int ksel  = blockIdx.z % 3;         // interleave windows across waves
    const int plane = blockIdx.z / 3;
    const int bx = blockIdx.x, by = blockIdx.y;

    if (ksel == 0)      run_stream<3, CHR>(pred, tgt, sbuf, wsum, bx, by, plane);
    else if (ksel == 1) run_stream<5, CHR>(pred, tgt, sbuf, wsum, bx, by, plane);
    else                run_stream<7, CHR>(pred, tgt, sbuf, wsum, bx, by, plane);
}

extern "C" void kernel_launch(void* const* d_in, const int* in_sizes, int n_in,
                              void* d_out, int out_size) {
    const float* pred = (const float*)d_in[0];
    const float* tgt  = (const float*)d_in[1];
    float* out = (float*)d_out;

    const int npix = in_sizes[0];               // 16*3*512*512
    const int planes = npix / (IMG * IMG);      // 48

    dim3 grid(2, IMG / CHR, planes * 3);        // 2 strips x 8 chunks x (planes*3K)

    init_acc_kernel<<<1, 1>>>();
    stat_all_kernel<<<grid, BW>>>(pred, tgt);

    const double scale = 1.0 / (12.0 * (double)npix);
    finalize_kernel<<<1, 1>>>(out, scale);
}